// round 1
// baseline (speedup 1.0000x reference)
#include <cuda_runtime.h>

#define D 32
#define MMAX 1024
#define BN 64
#define BM 128

// Precomputed per-center data, [d][m] layout for coalesced tile loads.
__device__ float g_w[D * MMAX];   // 1/sigma^2
__device__ float g_a[D * MMAX];   // -2*c/sigma^2
__device__ float g_cm[MMAX];      // sum_d c^2/sigma^2
__device__ float g_le[MMAX];      // log2(1/detS) = -0.5*(D*log2(2pi) + sum log2 sigma^2)

__global__ void rbf_precompute(const float* __restrict__ centers,
                               const float* __restrict__ sigma, int M) {
    int m = blockIdx.x * blockDim.x + threadIdx.x;
    if (m >= M) return;
    float cm = 0.0f, lg = 0.0f;
#pragma unroll
    for (int d = 0; d < D; d++) {
        float c  = centers[m * D + d];
        float s  = sigma[m * D + d];
        float s2 = s * s;
        float w  = 1.0f / s2;
        g_w[d * M + m] = w;
        g_a[d * M + m] = -2.0f * c * w;
        cm = fmaf(c * c, w, cm);
        lg += log2f(s2);
    }
    g_cm[m] = cm;
    const float LOG2_2PI = 2.6514961294723187f;
    g_le[m] = -0.5f * (D * LOG2_2PI + lg);
}

__global__ __launch_bounds__(256) void rbf_main(const float* __restrict__ x,
                                                float* __restrict__ out,
                                                int N, int M) {
    // Padded strides: 68 and 132 keep bank access conflict-free and 16B-aligned.
    __shared__ float xs [D * 68];
    __shared__ float x2s[D * 68];
    __shared__ float ws [D * 132];
    __shared__ float as_[D * 132];
    __shared__ float cs[BM];
    __shared__ float es[BM];

    const int tid = threadIdx.x;
    const int n0 = blockIdx.y * BN;
    const int m0 = blockIdx.x * BM;

    // Load x tile (coalesced gmem; 4-way-conflict smem writes, one-time cost).
    for (int idx = tid; idx < BN * D; idx += 256) {
        int n = idx >> 5;          // idx / 32
        int d = idx & 31;          // idx % 32
        float v = x[(size_t)(n0 + n) * D + d];
        xs [d * 68 + n] = v;
        x2s[d * 68 + n] = v * v;
    }
    // Load center tile (coalesced gmem, conflict-free smem writes).
    for (int idx = tid; idx < BM * D; idx += 256) {
        int d  = idx >> 7;         // idx / 128
        int ml = idx & 127;        // idx % 128
        ws [d * 132 + ml] = g_w[d * M + m0 + ml];
        as_[d * 132 + ml] = g_a[d * M + m0 + ml];
    }
    if (tid < BM) {
        cs[tid] = g_cm[m0 + tid];
        es[tid] = g_le[m0 + tid];
    }
    __syncthreads();

    const int tx = tid & 15;
    const int ty = tid >> 4;
    const int xoff  = ty * 4;
    const int woff0 = tx * 4;        // columns tx*4 .. tx*4+3
    const int woff1 = 64 + tx * 4;   // columns 64+tx*4 .. 64+tx*4+3

    float acc[4][8];
#pragma unroll
    for (int i = 0; i < 4; i++)
#pragma unroll
        for (int j = 0; j < 8; j++) acc[i][j] = 0.0f;

#pragma unroll 4
    for (int d = 0; d < D; d++) {
        float4 xv = *(const float4*)(xs  + d * 68 + xoff);
        float4 qv = *(const float4*)(x2s + d * 68 + xoff);
        float4 w0 = *(const float4*)(ws  + d * 132 + woff0);
        float4 w1 = *(const float4*)(ws  + d * 132 + woff1);
        float4 a0 = *(const float4*)(as_ + d * 132 + woff0);
        float4 a1 = *(const float4*)(as_ + d * 132 + woff1);
        float xr[4] = {xv.x, xv.y, xv.z, xv.w};
        float qr[4] = {qv.x, qv.y, qv.z, qv.w};
        float wr[8] = {w0.x, w0.y, w0.z, w0.w, w1.x, w1.y, w1.z, w1.w};
        float ar[8] = {a0.x, a0.y, a0.z, a0.w, a1.x, a1.y, a1.z, a1.w};
#pragma unroll
        for (int i = 0; i < 4; i++)
#pragma unroll
            for (int j = 0; j < 8; j++)
                acc[i][j] = fmaf(qr[i], wr[j], fmaf(xr[i], ar[j], acc[i][j]));
    }

    // Epilogue: out = exp2(X * (-0.5*log2 e) + log2(1/detS)), vectorized stores.
    const float CEXP = -0.7213475204444817f;
#pragma unroll
    for (int i = 0; i < 4; i++) {
        const int row = n0 + ty * 4 + i;
        float* orow = out + (size_t)row * M + m0;
#pragma unroll
        for (int h = 0; h < 2; h++) {
            const int cb = h * 64 + tx * 4;
            float X0 = acc[i][h * 4 + 0] + cs[cb + 0];
            float X1 = acc[i][h * 4 + 1] + cs[cb + 1];
            float X2 = acc[i][h * 4 + 2] + cs[cb + 2];
            float X3 = acc[i][h * 4 + 3] + cs[cb + 3];
            float4 r;
            r.x = exp2f(fmaf(X0, CEXP, es[cb + 0]));
            r.y = exp2f(fmaf(X1, CEXP, es[cb + 1]));
            r.z = exp2f(fmaf(X2, CEXP, es[cb + 2]));
            r.w = exp2f(fmaf(X3, CEXP, es[cb + 3]));
            *(float4*)(orow + cb) = r;
        }
    }
}

extern "C" void kernel_launch(void* const* d_in, const int* in_sizes, int n_in,
                              void* d_out, int out_size) {
    const float* x       = (const float*)d_in[0];
    const float* centers = (const float*)d_in[1];
    const float* sigma   = (const float*)d_in[2];
    float* out = (float*)d_out;

    int N = in_sizes[0] / D;
    int M = in_sizes[1] / D;

    rbf_precompute<<<(M + 255) / 256, 256>>>(centers, sigma, M);

    dim3 grid(M / BM, N / BN);
    rbf_main<<<grid, 256>>>(x, out, N, M);
}

// round 2
// speedup vs baseline: 1.0568x; 1.0568x over previous
#include <cuda_runtime.h>

#define D  32
#define BN 128
#define BM 128
#define MMAX 1024

// Precomputed per-center data, [d][m] layout, pre-scaled by CEXP = -0.5*log2(e)
// so the accumulator directly builds the log2-space exponent.
__device__ float g_w[D * MMAX];   // CEXP / sigma^2
__device__ float g_a[D * MMAX];   // CEXP * (-2 c / sigma^2)
__device__ float g_eb[MMAX];      // CEXP * sum(c^2/s^2) + log2(1/detS)

__device__ __forceinline__ unsigned long long pack2(float v) {
    unsigned long long r;
    asm("mov.b64 %0, {%1, %2};" : "=l"(r) : "f"(v), "f"(v));
    return r;
}
__device__ __forceinline__ unsigned long long mul2(unsigned long long a, unsigned long long b) {
    unsigned long long r;
    asm("mul.rn.f32x2 %0, %1, %2;" : "=l"(r) : "l"(a), "l"(b));
    return r;
}
__device__ __forceinline__ unsigned long long fma2(unsigned long long a, unsigned long long b,
                                                   unsigned long long c) {
    unsigned long long r;
    asm("fma.rn.f32x2 %0, %1, %2, %3;" : "=l"(r) : "l"(a), "l"(b), "l"(c));
    return r;
}
__device__ __forceinline__ void unpack2(unsigned long long a, float& lo, float& hi) {
    asm("mov.b64 {%0, %1}, %2;" : "=f"(lo), "=f"(hi) : "l"(a));
}
__device__ __forceinline__ float ex2(float v) {
    float r;
    asm("ex2.approx.ftz.f32 %0, %1;" : "=f"(r) : "f"(v));
    return r;
}

__global__ void rbf_precompute(const float* __restrict__ centers,
                               const float* __restrict__ sigma, int M) {
    int m = blockIdx.x * blockDim.x + threadIdx.x;
    if (m >= M) return;
    const float CEXP = -0.7213475204444817f;     // -0.5 * log2(e)
    const float LOG2_2PI = 2.6514961294723187f;
    float cm = 0.0f, lg = 0.0f;
#pragma unroll
    for (int d = 0; d < D; d++) {
        float c  = centers[m * D + d];
        float s  = sigma[m * D + d];
        float s2 = s * s;
        float w  = 1.0f / s2;
        g_w[d * M + m] = CEXP * w;
        g_a[d * M + m] = CEXP * (-2.0f * c * w);
        cm = fmaf(c * c, w, cm);
        lg += __log2f(s2);
    }
    g_eb[m] = fmaf(CEXP, cm, -0.5f * (D * LOG2_2PI + lg));
}

__global__ __launch_bounds__(256, 2) void rbf_main(const float* __restrict__ x,
                                                   float* __restrict__ out,
                                                   int N, int M) {
    __shared__ float xs [D * BN];   // [d][n], stride 128 (16 KB)
    __shared__ float ws [D * BM];   // [d][m], stride 128 (16 KB)
    __shared__ float as_[D * BM];   // [d][m], stride 128 (16 KB)  total = 48 KB exactly

    const int tid = threadIdx.x;
    const int n0 = blockIdx.y * BN;
    const int m0 = blockIdx.x * BM;

    // x tile: float4 gmem loads (coalesced), scattered smem writes (8-way, one-time).
    for (int idx = tid; idx < BN * (D / 4); idx += 256) {
        int n  = idx >> 3;
        int dq = idx & 7;
        float4 v = *(const float4*)(x + (size_t)(n0 + n) * D + dq * 4);
        xs[(dq * 4 + 0) * BN + n] = v.x;
        xs[(dq * 4 + 1) * BN + n] = v.y;
        xs[(dq * 4 + 2) * BN + n] = v.z;
        xs[(dq * 4 + 3) * BN + n] = v.w;
    }
    // center tiles: fully coalesced, conflict-free.
    for (int idx = tid; idx < D * BM; idx += 256) {
        int d  = idx >> 7;
        int ml = idx & 127;
        ws [idx] = g_w[d * M + m0 + ml];
        as_[idx] = g_a[d * M + m0 + ml];
    }
    __syncthreads();

    const int tx = tid & 15;
    const int ty = tid >> 4;
    const float* xbase = xs  + ty * 8;
    const float* wbase = ws  + tx * 8;
    const float* abase = as_ + tx * 8;

    unsigned long long acc[4][8];   // acc[i2][j]: rows (2*i2, 2*i2+1), col j
#pragma unroll
    for (int i = 0; i < 4; i++)
#pragma unroll
        for (int j = 0; j < 8; j++) acc[i][j] = 0ULL;

#pragma unroll 4
    for (int d = 0; d < D; d++) {
        ulonglong2 xp0 = *(const ulonglong2*)(xbase + d * BN);
        ulonglong2 xp1 = *(const ulonglong2*)(xbase + d * BN + 4);
        unsigned long long p[4] = {xp0.x, xp0.y, xp1.x, xp1.y};
        unsigned long long q[4];
#pragma unroll
        for (int i = 0; i < 4; i++) q[i] = mul2(p[i], p[i]);

        float4 w0 = *(const float4*)(wbase + d * BM);
        float4 w1 = *(const float4*)(wbase + d * BM + 4);
        float4 a0 = *(const float4*)(abase + d * BM);
        float4 a1 = *(const float4*)(abase + d * BM + 4);
        float wr[8] = {w0.x, w0.y, w0.z, w0.w, w1.x, w1.y, w1.z, w1.w};
        float ar[8] = {a0.x, a0.y, a0.z, a0.w, a1.x, a1.y, a1.z, a1.w};

#pragma unroll
        for (int j = 0; j < 8; j++) {
            unsigned long long wsp = pack2(wr[j]);
            unsigned long long asp = pack2(ar[j]);
#pragma unroll
            for (int i = 0; i < 4; i++)
                acc[i][j] = fma2(q[i], wsp, fma2(p[i], asp, acc[i][j]));
        }
    }

    // Epilogue: out = exp2(acc + eb), vectorized stores.
    float eb[8];
    {
        float4 e0 = *(const float4*)(g_eb + m0 + tx * 8);
        float4 e1 = *(const float4*)(g_eb + m0 + tx * 8 + 4);
        eb[0]=e0.x; eb[1]=e0.y; eb[2]=e0.z; eb[3]=e0.w;
        eb[4]=e1.x; eb[5]=e1.y; eb[6]=e1.z; eb[7]=e1.w;
    }
#pragma unroll
    for (int i2 = 0; i2 < 4; i2++) {
        float lo[8], hi[8];
#pragma unroll
        for (int j = 0; j < 8; j++) {
            float l, h;
            unpack2(acc[i2][j], l, h);
            lo[j] = ex2(l + eb[j]);
            hi[j] = ex2(h + eb[j]);
        }
        const int r0 = n0 + ty * 8 + 2 * i2;
        float* o0 = out + (size_t)r0 * M + m0 + tx * 8;
        float* o1 = o0 + M;
        *(float4*)(o0)     = make_float4(lo[0], lo[1], lo[2], lo[3]);
        *(float4*)(o0 + 4) = make_float4(lo[4], lo[5], lo[6], lo[7]);
        *(float4*)(o1)     = make_float4(hi[0], hi[1], hi[2], hi[3]);
        *(float4*)(o1 + 4) = make_float4(hi[4], hi[5], hi[6], hi[7]);
    }
}

extern "C" void kernel_launch(void* const* d_in, const int* in_sizes, int n_in,
                              void* d_out, int out_size) {
    const float* x       = (const float*)d_in[0];
    const float* centers = (const float*)d_in[1];
    const float* sigma   = (const float*)d_in[2];
    float* out = (float*)d_out;

    int N = in_sizes[0] / D;
    int M = in_sizes[1] / D;

    rbf_precompute<<<(M + 127) / 128, 128>>>(centers, sigma, M);

    dim3 grid(M / BM, N / BN);
    rbf_main<<<grid, 256>>>(x, out, N, M);
}